// round 4
// baseline (speedup 1.0000x reference)
#include <cuda_runtime.h>
#include <cstdint>

#define BATCH 4
#define CH    512
#define NPTS  4096
#define MROWS (BATCH * NPTS)   // 16384
#define KNN   5

// ---------------- scratch (static device globals; no allocation) ----------------
__device__ float g_xt[(size_t)MROWS * CH];        // current features [M, C]
__device__ float g_feat[(size_t)MROWS * 2 * CH];  // interleaved [x_c, maxrel_c]
__device__ float g_y[(size_t)MROWS * CH];         // pre-BN GEMM output
__device__ float g_h[(size_t)MROWS * (CH / 2)];   // classifier hidden
__device__ int   g_idx[MROWS * KNN];              // knn indices (per-batch local)
__device__ float g_sum[CH];
__device__ float g_sumsq[CH];

// ---------------- transpose: x [B,C,N] -> g_xt [B*N, C] ----------------
__global__ void transpose_kernel(const float* __restrict__ x) {
    __shared__ float tile[32][33];
    int b = blockIdx.z;
    int n0 = blockIdx.x * 32, c0 = blockIdx.y * 32;
    int tx = threadIdx.x, ty = threadIdx.y;  // (32, 8)
#pragma unroll
    for (int i = 0; i < 4; i++) {
        int c = c0 + ty + i * 8;
        tile[ty + i * 8][tx] = x[((size_t)(b * CH + c)) * NPTS + n0 + tx];
    }
    __syncthreads();
#pragma unroll
    for (int i = 0; i < 4; i++) {
        int n = n0 + ty + i * 8;
        g_xt[((size_t)(b * NPTS + n)) * CH + c0 + tx] = tile[tx][ty + i * 8];
    }
}

// ---------------- KNN: top-5 nearest (incl. self), matches jax.lax.top_k ties ----
// Rounding model of the reference pipeline:
//   d2   = rn( rn(x*x) + rn(y*y) )           (XLA elementwise+reduce fusion, no fma)
//   dot  = fma(yi, yj, rn(xi*xj))            (cuBLAS/Eigen fp32 gemm K=2, acc=0)
//   dist = rn( rn(d2i + d2j) - 2*dot )       (elementwise fusion; x2 & sub exact rn)
#define LTC(da, ia, db, ib) ((da) < (db) || ((da) == (db) && (ia) < (ib)))

__global__ void knn_kernel(const float* __restrict__ pos) {
    __shared__ float sx[NPTS];
    __shared__ float sy[NPTS];
    __shared__ float sd[NPTS];
    int b = blockIdx.y;
    const float* p = pos + (size_t)b * NPTS * 2;
    for (int j = threadIdx.x; j < NPTS; j += blockDim.x) {
        float xx = p[2 * j], yy = p[2 * j + 1];
        sx[j] = xx; sy[j] = yy;
        sd[j] = __fadd_rn(__fmul_rn(xx, xx), __fmul_rn(yy, yy));  // add-form d2
    }
    __syncthreads();

    int warp = threadIdx.x >> 5, lane = threadIdx.x & 31;
    int q = blockIdx.x * (blockDim.x >> 5) + warp;  // query index within batch

    float xi = sx[q], yi = sy[q], d2i = sd[q];
    const float INF = __int_as_float(0x7f800000);
    float d0 = INF, d1 = INF, d2 = INF, d3 = INF, d4 = INF;
    int   i0 = 0x7fffffff, i1 = 0x7fffffff, i2 = 0x7fffffff, i3 = 0x7fffffff, i4 = 0x7fffffff;

    for (int j = lane; j < NPTS; j += 32) {
        float dot  = __fmaf_rn(yi, sy[j], __fmul_rn(xi, sx[j]));  // fma-form dot (gemm)
        float dist = __fadd_rn(__fadd_rn(d2i, sd[j]), -__fmul_rn(2.0f, dot));
        if (LTC(dist, j, d4, i4)) {
            d4 = dist; i4 = j;
            if (LTC(d4, i4, d3, i3)) { float tf = d3; d3 = d4; d4 = tf; int ti = i3; i3 = i4; i4 = ti; }
            if (LTC(d3, i3, d2, i2)) { float tf = d2; d2 = d3; d3 = tf; int ti = i2; i2 = i3; i3 = ti; }
            if (LTC(d2, i2, d1, i1)) { float tf = d1; d1 = d2; d2 = tf; int ti = i1; i1 = i2; i2 = ti; }
            if (LTC(d1, i1, d0, i0)) { float tf = d0; d0 = d1; d1 = tf; int ti = i0; i0 = i1; i1 = ti; }
        }
    }

    // merge: 5 rounds of warp argmin; winner lane pops its sorted head
#pragma unroll
    for (int k = 0; k < KNN; k++) {
        float od = d0; int oi = i0;
#pragma unroll
        for (int off = 16; off; off >>= 1) {
            float td = __shfl_down_sync(0xffffffffu, od, off);
            int   ti = __shfl_down_sync(0xffffffffu, oi, off);
            if (LTC(td, ti, od, oi)) { od = td; oi = ti; }
        }
        od = __shfl_sync(0xffffffffu, od, 0);
        oi = __shfl_sync(0xffffffffu, oi, 0);
        if (oi == i0) {  // indices unique across lanes -> winner lane only
            d0 = d1; i0 = i1; d1 = d2; i1 = i2; d2 = d3; i2 = i3; d3 = d4; i3 = i4;
            d4 = INF; i4 = 0x7fffffff;
        }
        if (lane == 0) g_idx[((size_t)(b * NPTS + q)) * KNN + k] = oi;
    }
}

// ---------------- feat: gather + maxrel, interleaved write ----------------
__global__ void feat_kernel() {
    int r = blockIdx.x;
    __shared__ int nb[KNN];
    int b = r >> 12;  // r / NPTS
    if (threadIdx.x < KNN) nb[threadIdx.x] = b * NPTS + g_idx[r * KNN + threadIdx.x];
    __syncthreads();
    int n0 = nb[0], n1 = nb[1], n2 = nb[2], n3 = nb[3], n4 = nb[4];
    const float* xr = g_xt + (size_t)r * CH;
    float2* fr = (float2*)(g_feat + (size_t)r * 2 * CH);
    for (int c = threadIdx.x; c < CH; c += blockDim.x) {
        float s = xr[c];
        float m = g_xt[(size_t)n0 * CH + c] - s;
        m = fmaxf(m, g_xt[(size_t)n1 * CH + c] - s);
        m = fmaxf(m, g_xt[(size_t)n2 * CH + c] - s);
        m = fmaxf(m, g_xt[(size_t)n3 * CH + c] - s);
        m = fmaxf(m, g_xt[(size_t)n4 * CH + c] - s);
        fr[c] = make_float2(s, m);
    }
}

// ---------------- sgemm: C[M,N] = A[M,K] * B[N,K]^T + bias, optional relu ----------------
// Exact fp32. BM=BN=128, BK=8, 256 threads, 8x8 per thread.
template <int RELU>
__global__ void __launch_bounds__(256) sgemm_nt(const float* __restrict__ A,
                                                const float* __restrict__ Bm,
                                                const float* __restrict__ bias,
                                                float* __restrict__ Cm,
                                                int Mm, int Nn, int Kk) {
    __shared__ float As[8][128];
    __shared__ float Bs[8][128];
    int t = threadIdx.x;
    int row0 = blockIdx.y * 128;
    int col0 = blockIdx.x * 128;
    int arow = t >> 1;
    int acol = (t & 1) * 4;
    const float* Aptr = A + (size_t)(row0 + arow) * Kk + acol;
    const float* Bptr = Bm + (size_t)(col0 + arow) * Kk + acol;
    int ty = t >> 4, tx = t & 15;
    float acc[8][8];
#pragma unroll
    for (int i = 0; i < 8; i++)
#pragma unroll
        for (int j = 0; j < 8; j++) acc[i][j] = 0.f;

    for (int k0 = 0; k0 < Kk; k0 += 8) {
        float4 av = *(const float4*)(Aptr + k0);
        float4 bv = *(const float4*)(Bptr + k0);
        As[acol + 0][arow] = av.x; As[acol + 1][arow] = av.y;
        As[acol + 2][arow] = av.z; As[acol + 3][arow] = av.w;
        Bs[acol + 0][arow] = bv.x; Bs[acol + 1][arow] = bv.y;
        Bs[acol + 2][arow] = bv.z; Bs[acol + 3][arow] = bv.w;
        __syncthreads();
#pragma unroll
        for (int kk = 0; kk < 8; kk++) {
            float ra[8], rb[8];
#pragma unroll
            for (int i = 0; i < 8; i++) ra[i] = As[kk][ty * 8 + i];
#pragma unroll
            for (int j = 0; j < 8; j++) rb[j] = Bs[kk][tx * 8 + j];
#pragma unroll
            for (int i = 0; i < 8; i++)
#pragma unroll
                for (int j = 0; j < 8; j++) acc[i][j] = fmaf(ra[i], rb[j], acc[i][j]);
        }
        __syncthreads();
    }
#pragma unroll
    for (int i = 0; i < 8; i++) {
        int row = row0 + ty * 8 + i;
        float* cp = Cm + (size_t)row * Nn + col0 + tx * 8;
#pragma unroll
        for (int j = 0; j < 8; j++) {
            float v = acc[i][j] + bias[col0 + tx * 8 + j];
            if (RELU) v = fmaxf(v, 0.f);
            cp[j] = v;
        }
    }
}

// ---------------- BatchNorm ----------------
__global__ void zero_stats() {
    g_sum[threadIdx.x] = 0.f;
    g_sumsq[threadIdx.x] = 0.f;
}

__global__ void bn_stats() {
    int r0 = blockIdx.x * 128;
    int c0 = threadIdx.x, c1 = threadIdx.x + 256;
    float s0 = 0.f, s1 = 0.f, q0 = 0.f, q1 = 0.f;
    for (int i = 0; i < 128; i++) {
        const float* row = g_y + (size_t)(r0 + i) * CH;
        float v0 = row[c0], v1 = row[c1];
        s0 += v0; q0 += v0 * v0;
        s1 += v1; q1 += v1 * v1;
    }
    atomicAdd(&g_sum[c0], s0); atomicAdd(&g_sumsq[c0], q0);
    atomicAdd(&g_sum[c1], s1); atomicAdd(&g_sumsq[c1], q1);
}

__global__ void bn_apply(const float* __restrict__ gamma, const float* __restrict__ beta) {
    int i = blockIdx.x * blockDim.x + threadIdx.x;
    int c = i & (CH - 1);
    const float inv = 1.0f / (float)MROWS;
    float mean = g_sum[c] * inv;
    float var  = g_sumsq[c] * inv - mean * mean;
    float v = (g_y[i] - mean) * rsqrtf(var + 1e-5f) * gamma[c] + beta[c];
    g_xt[i] = fmaxf(v, 0.f);
}

// ---------------- final tiny GEMM: out[M,5] = h[M,256] @ Wc2[5,256]^T + bc2 -----
__global__ void final_kernel(const float* __restrict__ Wc2, const float* __restrict__ bc2,
                             float* __restrict__ out) {
    __shared__ float w[5 * 256];
    for (int i = threadIdx.x; i < 5 * 256; i += blockDim.x) w[i] = Wc2[i];
    __syncthreads();
    int warp = threadIdx.x >> 5, lane = threadIdx.x & 31;
    int r = blockIdx.x * (blockDim.x >> 5) + warp;
    const float* h = g_h + (size_t)r * 256;
    float a0 = 0, a1 = 0, a2 = 0, a3 = 0, a4 = 0;
    for (int c = lane; c < 256; c += 32) {
        float hv = h[c];
        a0 = fmaf(hv, w[0 * 256 + c], a0);
        a1 = fmaf(hv, w[1 * 256 + c], a1);
        a2 = fmaf(hv, w[2 * 256 + c], a2);
        a3 = fmaf(hv, w[3 * 256 + c], a3);
        a4 = fmaf(hv, w[4 * 256 + c], a4);
    }
#pragma unroll
    for (int off = 16; off; off >>= 1) {
        a0 += __shfl_xor_sync(0xffffffffu, a0, off);
        a1 += __shfl_xor_sync(0xffffffffu, a1, off);
        a2 += __shfl_xor_sync(0xffffffffu, a2, off);
        a3 += __shfl_xor_sync(0xffffffffu, a3, off);
        a4 += __shfl_xor_sync(0xffffffffu, a4, off);
    }
    if (lane == 0) {
        float* o = out + (size_t)r * 5;
        o[0] = a0 + bc2[0];
        o[1] = a1 + bc2[1];
        o[2] = a2 + bc2[2];
        o[3] = a3 + bc2[3];
        o[4] = a4 + bc2[4];
    }
}

// ---------------- launch ----------------
extern "C" void kernel_launch(void* const* d_in, const int* in_sizes, int n_in,
                              void* d_out, int out_size) {
    const float* x    = (const float*)d_in[0];
    const float* pos  = (const float*)d_in[1];
    const float* W[3]  = {(const float*)d_in[2], (const float*)d_in[6], (const float*)d_in[10]};
    const float* bb[3] = {(const float*)d_in[3], (const float*)d_in[7], (const float*)d_in[11]};
    const float* gg[3] = {(const float*)d_in[4], (const float*)d_in[8], (const float*)d_in[12]};
    const float* be[3] = {(const float*)d_in[5], (const float*)d_in[9], (const float*)d_in[13]};
    const float* Wc1 = (const float*)d_in[14];
    const float* bc1 = (const float*)d_in[15];
    const float* Wc2 = (const float*)d_in[16];
    const float* bc2 = (const float*)d_in[17];
    float* out = (float*)d_out;

    float *p_xt, *p_feat, *p_y, *p_h;
    cudaGetSymbolAddress((void**)&p_xt, g_xt);
    cudaGetSymbolAddress((void**)&p_feat, g_feat);
    cudaGetSymbolAddress((void**)&p_y, g_y);
    cudaGetSymbolAddress((void**)&p_h, g_h);

    transpose_kernel<<<dim3(NPTS / 32, CH / 32, BATCH), dim3(32, 8)>>>(x);
    knn_kernel<<<dim3(NPTS / 8, BATCH), 256>>>(pos);

    for (int i = 0; i < 3; i++) {
        feat_kernel<<<MROWS, 128>>>();
        sgemm_nt<0><<<dim3(CH / 128, MROWS / 128), 256>>>(p_feat, W[i], bb[i], p_y,
                                                          MROWS, CH, 2 * CH);
        zero_stats<<<1, CH>>>();
        bn_stats<<<MROWS / 128, 256>>>();
        bn_apply<<<(MROWS * CH) / 256, 256>>>(gg[i], be[i]);
    }

    // classifier
    sgemm_nt<1><<<dim3((CH / 2) / 128, MROWS / 128), 256>>>(p_xt, Wc1, bc1, p_h,
                                                            MROWS, CH / 2, CH);
    final_kernel<<<MROWS / 8, 256>>>(Wc2, bc2, out);
}

// round 6
// speedup vs baseline: 2.0392x; 2.0392x over previous
#include <cuda_runtime.h>
#include <cuda_bf16.h>
#include <cstdint>

#define BATCH 4
#define CH    512
#define NPTS  4096
#define MROWS (BATCH * NPTS)   // 16384
#define KNN   5
#define KDIM  (2 * CH)         // 1024

// ================= PTX helpers (baseline ISA only — no sm_103a features) =========
__device__ __forceinline__ uint32_t smem_u32(const void* p) {
    return (uint32_t)__cvta_generic_to_shared((void*)p);
}
#define SWZ(o) ((o) ^ (((o) >> 3) & 0x70))

__device__ __forceinline__ void ldsm_x4(uint32_t (&r)[4], uint32_t addr) {
    asm volatile("ldmatrix.sync.aligned.m8n8.x4.shared.b16 {%0,%1,%2,%3}, [%4];"
                 : "=r"(r[0]), "=r"(r[1]), "=r"(r[2]), "=r"(r[3]) : "r"(addr));
}
__device__ __forceinline__ void ldsm_x2(uint32_t (&r)[2], uint32_t addr) {
    asm volatile("ldmatrix.sync.aligned.m8n8.x2.shared.b16 {%0,%1}, [%2];"
                 : "=r"(r[0]), "=r"(r[1]) : "r"(addr));
}
__device__ __forceinline__ void mma16816(float (&c)[4], const uint32_t (&a)[4],
                                         const uint32_t (&b)[2]) {
    asm volatile("mma.sync.aligned.m16n8k16.row.col.f32.bf16.bf16.f32 "
                 "{%0,%1,%2,%3}, {%4,%5,%6,%7}, {%8,%9}, {%0,%1,%2,%3};"
                 : "+f"(c[0]), "+f"(c[1]), "+f"(c[2]), "+f"(c[3])
                 : "r"(a[0]), "r"(a[1]), "r"(a[2]), "r"(a[3]), "r"(b[0]), "r"(b[1]));
}
#define CP_ASYNC16(dst, src) \
    asm volatile("cp.async.cg.shared.global [%0], [%1], 16;" :: "r"(dst), "l"(src))
#define CP_COMMIT() asm volatile("cp.async.commit_group;" ::: "memory")
#define CP_WAIT1()  asm volatile("cp.async.wait_group 1;" ::: "memory")
#define CP_WAIT0()  asm volatile("cp.async.wait_group 0;" ::: "memory")

// ================= scratch (static device globals; no allocation) =================
__device__ float g_xt[(size_t)MROWS * CH];
__device__ __align__(16) __nv_bfloat16 g_Ahi[(size_t)MROWS * KDIM];
__device__ __align__(16) __nv_bfloat16 g_Alo[(size_t)MROWS * KDIM];
__device__ __align__(16) __nv_bfloat16 g_Xhi[(size_t)MROWS * CH];
__device__ __align__(16) __nv_bfloat16 g_Xlo[(size_t)MROWS * CH];
__device__ __align__(16) __nv_bfloat16 g_Whi[(size_t)3 * CH * KDIM];
__device__ __align__(16) __nv_bfloat16 g_Wlo[(size_t)3 * CH * KDIM];
__device__ __align__(16) __nv_bfloat16 g_Chi[(size_t)(CH / 2) * CH];
__device__ __align__(16) __nv_bfloat16 g_Clo[(size_t)(CH / 2) * CH];
__device__ float g_y[(size_t)MROWS * CH];
__device__ float g_h[(size_t)MROWS * (CH / 2)];
__device__ int   g_idx[MROWS * KNN];
__device__ float g_sum[CH];
__device__ float g_sumsq[CH];

__device__ __forceinline__ void split_bf16(float x, __nv_bfloat16& h, __nv_bfloat16& l) {
    h = __float2bfloat16(x);
    l = __float2bfloat16(x - __bfloat162float(h));
}

// ---------------- transpose: x [B,C,N] -> g_xt [B*N, C] ----------------
__global__ void transpose_kernel(const float* __restrict__ x) {
    __shared__ float tile[32][33];
    int b = blockIdx.z;
    int n0 = blockIdx.x * 32, c0 = blockIdx.y * 32;
    int tx = threadIdx.x, ty = threadIdx.y;  // (32, 8)
#pragma unroll
    for (int i = 0; i < 4; i++) {
        int c = c0 + ty + i * 8;
        tile[ty + i * 8][tx] = x[((size_t)(b * CH + c)) * NPTS + n0 + tx];
    }
    __syncthreads();
#pragma unroll
    for (int i = 0; i < 4; i++) {
        int n = n0 + ty + i * 8;
        g_xt[((size_t)(b * NPTS + n)) * CH + c0 + tx] = tile[tx][ty + i * 8];
    }
}

// ---------------- KNN (bit-exact vs reference; DO NOT TOUCH) ----------------
#define LTC(da, ia, db, ib) ((da) < (db) || ((da) == (db) && (ia) < (ib)))

__global__ void knn_kernel(const float* __restrict__ pos) {
    __shared__ float sx[NPTS];
    __shared__ float sy[NPTS];
    __shared__ float sd[NPTS];
    int b = blockIdx.y;
    const float* p = pos + (size_t)b * NPTS * 2;
    for (int j = threadIdx.x; j < NPTS; j += blockDim.x) {
        float xx = p[2 * j], yy = p[2 * j + 1];
        sx[j] = xx; sy[j] = yy;
        sd[j] = __fadd_rn(__fmul_rn(xx, xx), __fmul_rn(yy, yy));  // add-form d2
    }
    __syncthreads();

    int warp = threadIdx.x >> 5, lane = threadIdx.x & 31;
    int q = blockIdx.x * (blockDim.x >> 5) + warp;

    float xi = sx[q], yi = sy[q], d2i = sd[q];
    const float INF = __int_as_float(0x7f800000);
    float d0 = INF, d1 = INF, d2 = INF, d3 = INF, d4 = INF;
    int   i0 = 0x7fffffff, i1 = 0x7fffffff, i2 = 0x7fffffff, i3 = 0x7fffffff, i4 = 0x7fffffff;

    for (int j = lane; j < NPTS; j += 32) {
        float dot  = __fmaf_rn(yi, sy[j], __fmul_rn(xi, sx[j]));  // fma-form dot
        float dist = __fadd_rn(__fadd_rn(d2i, sd[j]), -__fmul_rn(2.0f, dot));
        if (LTC(dist, j, d4, i4)) {
            d4 = dist; i4 = j;
            if (LTC(d4, i4, d3, i3)) { float tf = d3; d3 = d4; d4 = tf; int ti = i3; i3 = i4; i4 = ti; }
            if (LTC(d3, i3, d2, i2)) { float tf = d2; d2 = d3; d3 = tf; int ti = i2; i2 = i3; i3 = ti; }
            if (LTC(d2, i2, d1, i1)) { float tf = d1; d1 = d2; d2 = tf; int ti = i1; i1 = i2; i2 = ti; }
            if (LTC(d1, i1, d0, i0)) { float tf = d0; d0 = d1; d1 = tf; int ti = i0; i0 = i1; i1 = ti; }
        }
    }
#pragma unroll
    for (int k = 0; k < KNN; k++) {
        float od = d0; int oi = i0;
#pragma unroll
        for (int off = 16; off; off >>= 1) {
            float td = __shfl_down_sync(0xffffffffu, od, off);
            int   ti = __shfl_down_sync(0xffffffffu, oi, off);
            if (LTC(td, ti, od, oi)) { od = td; oi = ti; }
        }
        od = __shfl_sync(0xffffffffu, od, 0);
        oi = __shfl_sync(0xffffffffu, oi, 0);
        if (oi == i0) {
            d0 = d1; i0 = i1; d1 = d2; i1 = i2; d2 = d3; i2 = i3; d3 = d4; i3 = i4;
            d4 = INF; i4 = 0x7fffffff;
        }
        if (lane == 0) g_idx[((size_t)(b * NPTS + q)) * KNN + k] = oi;
    }
}

// ---------------- feat: gather + maxrel -> bf16 hi/lo, interleaved [x_c, m_c] ----
__global__ void feat_kernel() {
    int r = blockIdx.x;
    __shared__ int nb[KNN];
    if (threadIdx.x < KNN) nb[threadIdx.x] = (r >> 12) * NPTS + g_idx[r * KNN + threadIdx.x];
    __syncthreads();
    int n0 = nb[0], n1 = nb[1], n2 = nb[2], n3 = nb[3], n4 = nb[4];
    const float* xr = g_xt + (size_t)r * CH;
    __nv_bfloat162* ah = (__nv_bfloat162*)(g_Ahi + (size_t)r * KDIM);
    __nv_bfloat162* al = (__nv_bfloat162*)(g_Alo + (size_t)r * KDIM);
    for (int c = threadIdx.x; c < CH; c += blockDim.x) {
        float s = xr[c];
        float m = g_xt[(size_t)n0 * CH + c] - s;
        m = fmaxf(m, g_xt[(size_t)n1 * CH + c] - s);
        m = fmaxf(m, g_xt[(size_t)n2 * CH + c] - s);
        m = fmaxf(m, g_xt[(size_t)n3 * CH + c] - s);
        m = fmaxf(m, g_xt[(size_t)n4 * CH + c] - s);
        __nv_bfloat16 sh, sl, mh, ml;
        split_bf16(s, sh, sl);
        split_bf16(m, mh, ml);
        __nv_bfloat162 vh; vh.x = sh; vh.y = mh;
        __nv_bfloat162 vl; vl.x = sl; vl.y = ml;
        ah[c] = vh; al[c] = vl;
    }
}

// ---------------- weight split: fp32 -> bf16 hi/lo ----------------
__global__ void wsplit_kernel(const float* __restrict__ src, __nv_bfloat16* __restrict__ hi,
                              __nv_bfloat16* __restrict__ lo, int n) {
    int i = blockIdx.x * blockDim.x + threadIdx.x;
    if (i < n) {
        __nv_bfloat16 h, l;
        split_bf16(src[i], h, l);
        hi[i] = h; lo[i] = l;
    }
}

// ================= HMMA split-bf16 GEMM =================
// C[M,Nn] fp32 = Ahi*Bhi^T + Alo*Bhi^T + Ahi*Blo^T + bias, optional relu.
// CTA: 128x128 C-tile, 8 warps (2M x 4N), warp tile 64x32. K chunks of 64 bf16,
// 2-stage cp.async pipeline, SW128-swizzled smem, ldmatrix fragments.
#define SMEM_GEMM_BYTES (4 * 16384)  // A[2][128][64] + B[2][128][64] bf16

template <int RELU>
__global__ void __launch_bounds__(256) mma_gemm(
    const __nv_bfloat16* __restrict__ Ahi, const __nv_bfloat16* __restrict__ Alo,
    const __nv_bfloat16* __restrict__ Bhi, const __nv_bfloat16* __restrict__ Blo,
    const float* __restrict__ bias, float* __restrict__ C, int Kd, int Nn) {
    extern __shared__ char smem[];
    uint32_t sa = smem_u32(smem);
    uint32_t sbB = sa + 32768;
    int tid = threadIdx.x, lane = tid & 31, wid = tid >> 5;
    int wm = wid & 1, wn = wid >> 1;  // 2 x 4 warp grid
    int row0 = blockIdx.y * 128, col0 = blockIdx.x * 128;
    int KC = Kd >> 6, NIT = 3 * KC;

    float acc[4][4][4];
#pragma unroll
    for (int mi = 0; mi < 4; mi++)
#pragma unroll
        for (int ni = 0; ni < 4; ni++)
#pragma unroll
            for (int j = 0; j < 4; j++) acc[mi][ni][j] = 0.f;

    // per-thread load coords: 4 segs A + 4 segs B (16B each)
    int lr = tid >> 3, lg = tid & 7;  // row-base, 16B-group

    // prologue: stage 0 = (pass 0, chunk 0)
    {
        const __nv_bfloat16* As = Ahi;
        const __nv_bfloat16* Bs = Bhi;
#pragma unroll
        for (int i = 0; i < 4; i++) {
            int r = lr + i * 32;
            uint32_t dst = sa + SWZ((uint32_t)(r * 128 + lg * 16));
            CP_ASYNC16(dst, As + (size_t)(row0 + r) * Kd + lg * 8);
        }
#pragma unroll
        for (int i = 0; i < 4; i++) {
            int r = lr + i * 32;
            uint32_t dst = sbB + SWZ((uint32_t)(r * 128 + lg * 16));
            CP_ASYNC16(dst, Bs + (size_t)(col0 + r) * Kd + lg * 8);
        }
        CP_COMMIT();
    }

    for (int it = 0; it < NIT; it++) {
        int s = it & 1;
        if (it + 1 < NIT) {
            int nit = it + 1, s2 = 1 - s;
            int p = nit / KC, kc = nit - p * KC;
            const __nv_bfloat16* As = (p == 1) ? Alo : Ahi;
            const __nv_bfloat16* Bs = (p == 2) ? Blo : Bhi;
#pragma unroll
            for (int i = 0; i < 4; i++) {
                int r = lr + i * 32;
                uint32_t dst = sa + s2 * 16384 + SWZ((uint32_t)(r * 128 + lg * 16));
                CP_ASYNC16(dst, As + (size_t)(row0 + r) * Kd + kc * 64 + lg * 8);
            }
#pragma unroll
            for (int i = 0; i < 4; i++) {
                int r = lr + i * 32;
                uint32_t dst = sbB + s2 * 16384 + SWZ((uint32_t)(r * 128 + lg * 16));
                CP_ASYNC16(dst, Bs + (size_t)(col0 + r) * Kd + kc * 64 + lg * 8);
            }
            CP_COMMIT();
            CP_WAIT1();
        } else {
            CP_WAIT0();
        }
        __syncthreads();

        uint32_t abase = sa + s * 16384;
        uint32_t bbase = sbB + s * 16384;
#pragma unroll
        for (int kk = 0; kk < 4; kk++) {
            uint32_t af[4][4];
#pragma unroll
            for (int mi = 0; mi < 4; mi++) {
                int r = wm * 64 + mi * 16 + (lane & 15);
                uint32_t off = (uint32_t)(r * 128 + kk * 32 + (lane >> 4) * 16);
                ldsm_x4(af[mi], abase + SWZ(off));
            }
#pragma unroll
            for (int ni = 0; ni < 4; ni++) {
                uint32_t bfr[2];
                int r = wn * 32 + ni * 8 + (lane & 7);
                uint32_t off = (uint32_t)(r * 128 + kk * 32 + ((lane >> 3) & 1) * 16);
                ldsm_x2(bfr, bbase + SWZ(off));
#pragma unroll
                for (int mi = 0; mi < 4; mi++) mma16816(acc[mi][ni], af[mi], bfr);
            }
        }
        __syncthreads();
    }

    // epilogue: c frag -> gmem (+bias, optional relu)
#pragma unroll
    for (int mi = 0; mi < 4; mi++) {
        int row = row0 + wm * 64 + mi * 16 + (lane >> 2);
#pragma unroll
        for (int ni = 0; ni < 4; ni++) {
            int col = col0 + wn * 32 + ni * 8 + (lane & 3) * 2;
            float b0 = bias[col], b1 = bias[col + 1];
            float v0 = acc[mi][ni][0] + b0, v1 = acc[mi][ni][1] + b1;
            float v2 = acc[mi][ni][2] + b0, v3 = acc[mi][ni][3] + b1;
            if (RELU) {
                v0 = fmaxf(v0, 0.f); v1 = fmaxf(v1, 0.f);
                v2 = fmaxf(v2, 0.f); v3 = fmaxf(v3, 0.f);
            }
            float* cp0 = C + (size_t)row * Nn + col;
            float* cp1 = C + (size_t)(row + 8) * Nn + col;
            cp0[0] = v0; cp0[1] = v1;
            cp1[0] = v2; cp1[1] = v3;
        }
    }
}

// ---------------- BatchNorm ----------------
__global__ void zero_stats() {
    g_sum[threadIdx.x] = 0.f;
    g_sumsq[threadIdx.x] = 0.f;
}

__global__ void bn_stats() {
    int r0 = blockIdx.x * 128;
    int c0 = threadIdx.x, c1 = threadIdx.x + 256;
    float s0 = 0.f, s1 = 0.f, q0 = 0.f, q1 = 0.f;
    for (int i = 0; i < 128; i++) {
        const float* row = g_y + (size_t)(r0 + i) * CH;
        float v0 = row[c0], v1 = row[c1];
        s0 += v0; q0 += v0 * v0;
        s1 += v1; q1 += v1 * v1;
    }
    atomicAdd(&g_sum[c0], s0); atomicAdd(&g_sumsq[c0], q0);
    atomicAdd(&g_sum[c1], s1); atomicAdd(&g_sumsq[c1], q1);
}

__global__ void bn_apply(const float* __restrict__ gamma, const float* __restrict__ beta) {
    int i = blockIdx.x * blockDim.x + threadIdx.x;
    int c = i & (CH - 1);
    const float inv = 1.0f / (float)MROWS;
    float mean = g_sum[c] * inv;
    float var  = g_sumsq[c] * inv - mean * mean;
    float v = (g_y[i] - mean) * rsqrtf(var + 1e-5f) * gamma[c] + beta[c];
    v = fmaxf(v, 0.f);
    g_xt[i] = v;
    __nv_bfloat16 h, l;
    split_bf16(v, h, l);
    g_Xhi[i] = h; g_Xlo[i] = l;
}

// ---------------- final tiny GEMM: out[M,5] = h[M,256] @ Wc2[5,256]^T + bc2 -----
__global__ void final_kernel(const float* __restrict__ Wc2, const float* __restrict__ bc2,
                             float* __restrict__ out) {
    __shared__ float w[5 * 256];
    for (int i = threadIdx.x; i < 5 * 256; i += blockDim.x) w[i] = Wc2[i];
    __syncthreads();
    int warp = threadIdx.x >> 5, lane = threadIdx.x & 31;
    int r = blockIdx.x * (blockDim.x >> 5) + warp;
    const float* h = g_h + (size_t)r * 256;
    float a0 = 0, a1 = 0, a2 = 0, a3 = 0, a4 = 0;
    for (int c = lane; c < 256; c += 32) {
        float hv = h[c];
        a0 = fmaf(hv, w[0 * 256 + c], a0);
        a1 = fmaf(hv, w[1 * 256 + c], a1);
        a2 = fmaf(hv, w[2 * 256 + c], a2);
        a3 = fmaf(hv, w[3 * 256 + c], a3);
        a4 = fmaf(hv, w[4 * 256 + c], a4);
    }
#pragma unroll
    for (int off = 16; off; off >>= 1) {
        a0 += __shfl_xor_sync(0xffffffffu, a0, off);
        a1 += __shfl_xor_sync(0xffffffffu, a1, off);
        a2 += __shfl_xor_sync(0xffffffffu, a2, off);
        a3 += __shfl_xor_sync(0xffffffffu, a3, off);
        a4 += __shfl_xor_sync(0xffffffffu, a4, off);
    }
    if (lane == 0) {
        float* o = out + (size_t)r * 5;
        o[0] = a0 + bc2[0];
        o[1] = a1 + bc2[1];
        o[2] = a2 + bc2[2];
        o[3] = a3 + bc2[3];
        o[4] = a4 + bc2[4];
    }
}

// ---------------- launch ----------------
extern "C" void kernel_launch(void* const* d_in, const int* in_sizes, int n_in,
                              void* d_out, int out_size) {
    const float* x    = (const float*)d_in[0];
    const float* pos  = (const float*)d_in[1];
    const float* W[3]  = {(const float*)d_in[2], (const float*)d_in[6], (const float*)d_in[10]};
    const float* bb[3] = {(const float*)d_in[3], (const float*)d_in[7], (const float*)d_in[11]};
    const float* gg[3] = {(const float*)d_in[4], (const float*)d_in[8], (const float*)d_in[12]};
    const float* be[3] = {(const float*)d_in[5], (const float*)d_in[9], (const float*)d_in[13]};
    const float* Wc1 = (const float*)d_in[14];
    const float* bc1 = (const float*)d_in[15];
    const float* Wc2 = (const float*)d_in[16];
    const float* bc2 = (const float*)d_in[17];
    float* out = (float*)d_out;

    float *p_y, *p_h;
    __nv_bfloat16 *p_Ahi, *p_Alo, *p_Xhi, *p_Xlo, *p_Whi, *p_Wlo, *p_Chi, *p_Clo;
    cudaGetSymbolAddress((void**)&p_y, g_y);
    cudaGetSymbolAddress((void**)&p_h, g_h);
    cudaGetSymbolAddress((void**)&p_Ahi, g_Ahi);
    cudaGetSymbolAddress((void**)&p_Alo, g_Alo);
    cudaGetSymbolAddress((void**)&p_Xhi, g_Xhi);
    cudaGetSymbolAddress((void**)&p_Xlo, g_Xlo);
    cudaGetSymbolAddress((void**)&p_Whi, g_Whi);
    cudaGetSymbolAddress((void**)&p_Wlo, g_Wlo);
    cudaGetSymbolAddress((void**)&p_Chi, g_Chi);
    cudaGetSymbolAddress((void**)&p_Clo, g_Clo);

    cudaFuncSetAttribute(mma_gemm<0>, cudaFuncAttributeMaxDynamicSharedMemorySize, SMEM_GEMM_BYTES);
    cudaFuncSetAttribute(mma_gemm<1>, cudaFuncAttributeMaxDynamicSharedMemorySize, SMEM_GEMM_BYTES);

    transpose_kernel<<<dim3(NPTS / 32, CH / 32, BATCH), dim3(32, 8)>>>(x);
    knn_kernel<<<dim3(NPTS / 8, BATCH), 256>>>(pos);

    // weight conversions (deterministic; re-run every call)
    for (int i = 0; i < 3; i++)
        wsplit_kernel<<<(CH * KDIM) / 256, 256>>>(W[i], p_Whi + (size_t)i * CH * KDIM,
                                                  p_Wlo + (size_t)i * CH * KDIM, CH * KDIM);
    wsplit_kernel<<<((CH / 2) * CH) / 256, 256>>>(Wc1, p_Chi, p_Clo, (CH / 2) * CH);

    for (int i = 0; i < 3; i++) {
        feat_kernel<<<MROWS, 128>>>();
        mma_gemm<0><<<dim3(CH / 128, MROWS / 128), 256, SMEM_GEMM_BYTES>>>(
            p_Ahi, p_Alo, p_Whi + (size_t)i * CH * KDIM, p_Wlo + (size_t)i * CH * KDIM,
            bb[i], p_y, KDIM, CH);
        zero_stats<<<1, CH>>>();
        bn_stats<<<MROWS / 128, 256>>>();
        bn_apply<<<(MROWS * CH) / 256, 256>>>(gg[i], be[i]);
    }

    // classifier: h = relu(xt @ Wc1^T + bc1)
    mma_gemm<1><<<dim3((CH / 2) / 128, MROWS / 128), 256, SMEM_GEMM_BYTES>>>(
        p_Xhi, p_Xlo, p_Chi, p_Clo, bc1, p_h, CH, CH / 2);
    final_kernel<<<MROWS / 8, 256>>>(Wc2, bc2, out);
}

// round 7
// speedup vs baseline: 2.2205x; 1.0889x over previous
#include <cuda_runtime.h>
#include <cuda_bf16.h>
#include <cstdint>

#define BATCH 4
#define CH    512
#define NPTS  4096
#define MROWS (BATCH * NPTS)   // 16384
#define KNN   5
#define KDIM  (2 * CH)         // 1024

// ================= PTX helpers (baseline ISA only — no sm_103a features) =========
__device__ __forceinline__ uint32_t smem_u32(const void* p) {
    return (uint32_t)__cvta_generic_to_shared((void*)p);
}
#define SWZ(o) ((o) ^ (((o) >> 3) & 0x70))

__device__ __forceinline__ void ldsm_x4(uint32_t (&r)[4], uint32_t addr) {
    asm volatile("ldmatrix.sync.aligned.m8n8.x4.shared.b16 {%0,%1,%2,%3}, [%4];"
                 : "=r"(r[0]), "=r"(r[1]), "=r"(r[2]), "=r"(r[3]) : "r"(addr));
}
__device__ __forceinline__ void ldsm_x2(uint32_t (&r)[2], uint32_t addr) {
    asm volatile("ldmatrix.sync.aligned.m8n8.x2.shared.b16 {%0,%1}, [%2];"
                 : "=r"(r[0]), "=r"(r[1]) : "r"(addr));
}
__device__ __forceinline__ void mma16816(float (&c)[4], const uint32_t (&a)[4],
                                         const uint32_t (&b)[2]) {
    asm volatile("mma.sync.aligned.m16n8k16.row.col.f32.bf16.bf16.f32 "
                 "{%0,%1,%2,%3}, {%4,%5,%6,%7}, {%8,%9}, {%0,%1,%2,%3};"
                 : "+f"(c[0]), "+f"(c[1]), "+f"(c[2]), "+f"(c[3])
                 : "r"(a[0]), "r"(a[1]), "r"(a[2]), "r"(a[3]), "r"(b[0]), "r"(b[1]));
}
#define CP_ASYNC16(dst, src) \
    asm volatile("cp.async.cg.shared.global [%0], [%1], 16;" :: "r"(dst), "l"(src))
#define CP_COMMIT() asm volatile("cp.async.commit_group;" ::: "memory")
#define CP_WAIT2()  asm volatile("cp.async.wait_group 2;" ::: "memory")
#define CP_WAIT1()  asm volatile("cp.async.wait_group 1;" ::: "memory")
#define CP_WAIT0()  asm volatile("cp.async.wait_group 0;" ::: "memory")

// ================= scratch (static device globals; no allocation) =================
__device__ float g_xt[(size_t)MROWS * CH];        // only layer-1 input (from transpose)
__device__ __align__(16) __nv_bfloat16 g_Ahi[(size_t)MROWS * KDIM];
__device__ __align__(16) __nv_bfloat16 g_Alo[(size_t)MROWS * KDIM];
__device__ __align__(16) __nv_bfloat16 g_Xhi[(size_t)MROWS * CH];
__device__ __align__(16) __nv_bfloat16 g_Xlo[(size_t)MROWS * CH];
__device__ __align__(16) __nv_bfloat16 g_Whi[(size_t)3 * CH * KDIM];
__device__ __align__(16) __nv_bfloat16 g_Wlo[(size_t)3 * CH * KDIM];
__device__ __align__(16) __nv_bfloat16 g_Chi[(size_t)(CH / 2) * CH];
__device__ __align__(16) __nv_bfloat16 g_Clo[(size_t)(CH / 2) * CH];
__device__ float g_y[(size_t)MROWS * CH];
__device__ float g_h[(size_t)MROWS * (CH / 2)];
__device__ int   g_idx[MROWS * KNN];
__device__ float g_sum[CH];
__device__ float g_sumsq[CH];

__device__ __forceinline__ void split_bf16(float x, __nv_bfloat16& h, __nv_bfloat16& l) {
    h = __float2bfloat16(x);
    l = __float2bfloat16(x - __bfloat162float(h));
}

// ---------------- transpose: x [B,C,N] -> g_xt [B*N, C] ----------------
__global__ void transpose_kernel(const float* __restrict__ x) {
    __shared__ float tile[32][33];
    int b = blockIdx.z;
    int n0 = blockIdx.x * 32, c0 = blockIdx.y * 32;
    int tx = threadIdx.x, ty = threadIdx.y;  // (32, 8)
#pragma unroll
    for (int i = 0; i < 4; i++) {
        int c = c0 + ty + i * 8;
        tile[ty + i * 8][tx] = x[((size_t)(b * CH + c)) * NPTS + n0 + tx];
    }
    __syncthreads();
#pragma unroll
    for (int i = 0; i < 4; i++) {
        int n = n0 + ty + i * 8;
        g_xt[((size_t)(b * NPTS + n)) * CH + c0 + tx] = tile[tx][ty + i * 8];
    }
}

// ---------------- KNN (bit-exact vs reference; DO NOT TOUCH) ----------------
#define LTC(da, ia, db, ib) ((da) < (db) || ((da) == (db) && (ia) < (ib)))

__global__ void knn_kernel(const float* __restrict__ pos) {
    __shared__ float sx[NPTS];
    __shared__ float sy[NPTS];
    __shared__ float sd[NPTS];
    int b = blockIdx.y;
    const float* p = pos + (size_t)b * NPTS * 2;
    for (int j = threadIdx.x; j < NPTS; j += blockDim.x) {
        float xx = p[2 * j], yy = p[2 * j + 1];
        sx[j] = xx; sy[j] = yy;
        sd[j] = __fadd_rn(__fmul_rn(xx, xx), __fmul_rn(yy, yy));  // add-form d2
    }
    __syncthreads();

    int warp = threadIdx.x >> 5, lane = threadIdx.x & 31;
    int q = blockIdx.x * (blockDim.x >> 5) + warp;

    float xi = sx[q], yi = sy[q], d2i = sd[q];
    const float INF = __int_as_float(0x7f800000);
    float d0 = INF, d1 = INF, d2 = INF, d3 = INF, d4 = INF;
    int   i0 = 0x7fffffff, i1 = 0x7fffffff, i2 = 0x7fffffff, i3 = 0x7fffffff, i4 = 0x7fffffff;

    for (int j = lane; j < NPTS; j += 32) {
        float dot  = __fmaf_rn(yi, sy[j], __fmul_rn(xi, sx[j]));  // fma-form dot
        float dist = __fadd_rn(__fadd_rn(d2i, sd[j]), -__fmul_rn(2.0f, dot));
        if (LTC(dist, j, d4, i4)) {
            d4 = dist; i4 = j;
            if (LTC(d4, i4, d3, i3)) { float tf = d3; d3 = d4; d4 = tf; int ti = i3; i3 = i4; i4 = ti; }
            if (LTC(d3, i3, d2, i2)) { float tf = d2; d2 = d3; d3 = tf; int ti = i2; i2 = i3; i3 = ti; }
            if (LTC(d2, i2, d1, i1)) { float tf = d1; d1 = d2; d2 = tf; int ti = i1; i1 = i2; i2 = ti; }
            if (LTC(d1, i1, d0, i0)) { float tf = d0; d0 = d1; d1 = tf; int ti = i0; i0 = i1; i1 = ti; }
        }
    }
#pragma unroll
    for (int k = 0; k < KNN; k++) {
        float od = d0; int oi = i0;
#pragma unroll
        for (int off = 16; off; off >>= 1) {
            float td = __shfl_down_sync(0xffffffffu, od, off);
            int   ti = __shfl_down_sync(0xffffffffu, oi, off);
            if (LTC(td, ti, od, oi)) { od = td; oi = ti; }
        }
        od = __shfl_sync(0xffffffffu, od, 0);
        oi = __shfl_sync(0xffffffffu, oi, 0);
        if (oi == i0) {
            d0 = d1; i0 = i1; d1 = d2; i1 = i2; d2 = d3; i2 = i3; d3 = d4; i3 = i4;
            d4 = INF; i4 = 0x7fffffff;
        }
        if (lane == 0) g_idx[((size_t)(b * NPTS + q)) * KNN + k] = oi;
    }
}

// ---------------- feat (layer 1): gather + maxrel from fp32 g_xt ----------------
__global__ void feat_kernel() {
    int r = blockIdx.x;
    __shared__ int nb[KNN];
    if (threadIdx.x < KNN) nb[threadIdx.x] = (r >> 12) * NPTS + g_idx[r * KNN + threadIdx.x];
    __syncthreads();
    int n0 = nb[0], n1 = nb[1], n2 = nb[2], n3 = nb[3], n4 = nb[4];
    const float* xr = g_xt + (size_t)r * CH;
    __nv_bfloat162* ah = (__nv_bfloat162*)(g_Ahi + (size_t)r * KDIM);
    __nv_bfloat162* al = (__nv_bfloat162*)(g_Alo + (size_t)r * KDIM);
    for (int c = threadIdx.x; c < CH; c += blockDim.x) {
        float s = xr[c];
        float m = g_xt[(size_t)n0 * CH + c] - s;
        m = fmaxf(m, g_xt[(size_t)n1 * CH + c] - s);
        m = fmaxf(m, g_xt[(size_t)n2 * CH + c] - s);
        m = fmaxf(m, g_xt[(size_t)n3 * CH + c] - s);
        m = fmaxf(m, g_xt[(size_t)n4 * CH + c] - s);
        __nv_bfloat16 sh, sl, mh, ml;
        split_bf16(s, sh, sl);
        split_bf16(m, mh, ml);
        __nv_bfloat162 vh; vh.x = sh; vh.y = mh;
        __nv_bfloat162 vl; vl.x = sl; vl.y = ml;
        ah[c] = vh; al[c] = vl;
    }
}

// ---------------- bnfeat (layers 2,3): BN(g_y)+relu on the fly, gather + maxrel ---
__global__ void bnfeat_kernel(const float* __restrict__ gamma, const float* __restrict__ beta) {
    int r = blockIdx.x;
    __shared__ int nb[KNN];
    if (threadIdx.x < KNN) nb[threadIdx.x] = (r >> 12) * NPTS + g_idx[r * KNN + threadIdx.x];
    __syncthreads();
    int n0 = nb[0], n1 = nb[1], n2 = nb[2], n3 = nb[3], n4 = nb[4];
    const float* yr = g_y + (size_t)r * CH;
    __nv_bfloat162* ah = (__nv_bfloat162*)(g_Ahi + (size_t)r * KDIM);
    __nv_bfloat162* al = (__nv_bfloat162*)(g_Alo + (size_t)r * KDIM);
    const float inv = 1.0f / (float)MROWS;
    for (int c = threadIdx.x; c < CH; c += blockDim.x) {
        float mean = g_sum[c] * inv;
        float var  = g_sumsq[c] * inv - mean * mean;
        float rs = rsqrtf(var + 1e-5f);
        float gm = gamma[c], bt = beta[c];
        // norm(v) = (v-mean)*rs*gm + bt, then relu  (same op order as bn_apply)
        float s  = fmaxf((yr[c] - mean) * rs * gm + bt, 0.f);
        float a0 = fmaxf((g_y[(size_t)n0 * CH + c] - mean) * rs * gm + bt, 0.f);
        float a1 = fmaxf((g_y[(size_t)n1 * CH + c] - mean) * rs * gm + bt, 0.f);
        float a2 = fmaxf((g_y[(size_t)n2 * CH + c] - mean) * rs * gm + bt, 0.f);
        float a3 = fmaxf((g_y[(size_t)n3 * CH + c] - mean) * rs * gm + bt, 0.f);
        float a4 = fmaxf((g_y[(size_t)n4 * CH + c] - mean) * rs * gm + bt, 0.f);
        float m = fmaxf(fmaxf(fmaxf(a0 - s, a1 - s), fmaxf(a2 - s, a3 - s)), a4 - s);
        __nv_bfloat16 sh, sl, mh, ml;
        split_bf16(s, sh, sl);
        split_bf16(m, mh, ml);
        __nv_bfloat162 vh; vh.x = sh; vh.y = mh;
        __nv_bfloat162 vl; vl.x = sl; vl.y = ml;
        ah[c] = vh; al[c] = vl;
    }
}

// ---------------- bn_apply for classifier (layer 3 output -> Xhi/Xlo) ----------
__global__ void bn_apply_cls(const float* __restrict__ gamma, const float* __restrict__ beta) {
    int i = blockIdx.x * blockDim.x + threadIdx.x;
    int c = i & (CH - 1);
    const float inv = 1.0f / (float)MROWS;
    float mean = g_sum[c] * inv;
    float var  = g_sumsq[c] * inv - mean * mean;
    float v = fmaxf((g_y[i] - mean) * rsqrtf(var + 1e-5f) * gamma[c] + beta[c], 0.f);
    __nv_bfloat16 h, l;
    split_bf16(v, h, l);
    g_Xhi[i] = h; g_Xlo[i] = l;
}

// ---------------- all weight splits in one launch ----------------
#define W_ELEMS (CH * KDIM)            // 524288
#define C_ELEMS ((CH / 2) * CH)        // 131072
__global__ void wsplit_all(const float* __restrict__ w1, const float* __restrict__ w2,
                           const float* __restrict__ w3, const float* __restrict__ wc1) {
    int i = blockIdx.x * blockDim.x + threadIdx.x;
    const float* src; __nv_bfloat16 *hi, *lo; int k;
    if (i < W_ELEMS)            { src = w1;  hi = g_Whi;               lo = g_Wlo;               k = i; }
    else if (i < 2 * W_ELEMS)   { src = w2;  hi = g_Whi + W_ELEMS;     lo = g_Wlo + W_ELEMS;     k = i - W_ELEMS; }
    else if (i < 3 * W_ELEMS)   { src = w3;  hi = g_Whi + 2 * W_ELEMS; lo = g_Wlo + 2 * W_ELEMS; k = i - 2 * W_ELEMS; }
    else if (i < 3 * W_ELEMS + C_ELEMS) { src = wc1; hi = g_Chi;       lo = g_Clo;               k = i - 3 * W_ELEMS; }
    else return;
    __nv_bfloat16 h, l;
    split_bf16(src[k], h, l);
    hi[k] = h; lo[k] = l;
}

__global__ void zero_stats() {
    g_sum[threadIdx.x] = 0.f;
    g_sumsq[threadIdx.x] = 0.f;
}

// ================= HMMA split-bf16 GEMM, 3-stage pipeline, fused BN stats ========
// C[M,Nn] fp32 = Ahi*Bhi^T + Alo*Bhi^T + Ahi*Blo^T + bias, optional relu.
// CTA: 128x128, 8 warps (2M x 4N), warp 64x32. K chunks of 64 bf16, 3 cp.async stages.
#define STAGE_BYTES 32768
#define SMEM_GEMM_BYTES (3 * STAGE_BYTES)  // 96 KB

template <int RELU, int STATS>
__global__ void __launch_bounds__(256) mma_gemm(
    const __nv_bfloat16* __restrict__ Ahi, const __nv_bfloat16* __restrict__ Alo,
    const __nv_bfloat16* __restrict__ Bhi, const __nv_bfloat16* __restrict__ Blo,
    const float* __restrict__ bias, float* __restrict__ C, int Kd, int Nn) {
    extern __shared__ char smem[];
    uint32_t sb = smem_u32(smem);
    int tid = threadIdx.x, lane = tid & 31, wid = tid >> 5;
    int wm = wid & 1, wn = wid >> 1;  // 2 x 4 warp grid
    int row0 = blockIdx.y * 128, col0 = blockIdx.x * 128;
    int KC = Kd >> 6, NIT = 3 * KC;

    float acc[4][4][4];
#pragma unroll
    for (int mi = 0; mi < 4; mi++)
#pragma unroll
        for (int ni = 0; ni < 4; ni++)
#pragma unroll
            for (int j = 0; j < 4; j++) acc[mi][ni][j] = 0.f;

    int lr = tid >> 3, lg = tid & 7;

    // load chunk `idx` (global) into stage `st`
    auto load_chunk = [&](int idx, int st) {
        int p = idx / KC, kc = idx - p * KC;
        const __nv_bfloat16* As = (p == 1) ? Alo : Ahi;
        const __nv_bfloat16* Bs = (p == 2) ? Blo : Bhi;
        uint32_t abase = sb + st * STAGE_BYTES;
        uint32_t bbase = abase + 16384;
#pragma unroll
        for (int i = 0; i < 4; i++) {
            int r = lr + i * 32;
            CP_ASYNC16(abase + SWZ((uint32_t)(r * 128 + lg * 16)),
                       As + (size_t)(row0 + r) * Kd + kc * 64 + lg * 8);
        }
#pragma unroll
        for (int i = 0; i < 4; i++) {
            int r = lr + i * 32;
            CP_ASYNC16(bbase + SWZ((uint32_t)(r * 128 + lg * 16)),
                       Bs + (size_t)(col0 + r) * Kd + kc * 64 + lg * 8);
        }
        CP_COMMIT();
    };

    load_chunk(0, 0);
    load_chunk(1, 1);

    for (int it = 0; it < NIT; it++) {
        int s = it % 3;
        if (it + 2 < NIT) { load_chunk(it + 2, (it + 2) % 3); CP_WAIT2(); }
        else if (it + 1 < NIT) { CP_WAIT1(); }
        else { CP_WAIT0(); }
        __syncthreads();

        uint32_t abase = sb + s * STAGE_BYTES;
        uint32_t bbase = abase + 16384;
#pragma unroll
        for (int kk = 0; kk < 4; kk++) {
            uint32_t af[4][4];
#pragma unroll
            for (int mi = 0; mi < 4; mi++) {
                int r = wm * 64 + mi * 16 + (lane & 15);
                uint32_t off = (uint32_t)(r * 128 + kk * 32 + (lane >> 4) * 16);
                ldsm_x4(af[mi], abase + SWZ(off));
            }
#pragma unroll
            for (int ni = 0; ni < 4; ni++) {
                uint32_t bfr[2];
                int r = wn * 32 + ni * 8 + (lane & 7);
                uint32_t off = (uint32_t)(r * 128 + kk * 32 + ((lane >> 3) & 1) * 16);
                ldsm_x2(bfr, bbase + SWZ(off));
#pragma unroll
                for (int mi = 0; mi < 4; mi++) mma16816(acc[mi][ni], af[mi], bfr);
            }
        }
        __syncthreads();
    }

    // epilogue: +bias, optional relu, store; optional fused column stats
    float s_[4][2], q_[4][2];
    if (STATS) {
#pragma unroll
        for (int ni = 0; ni < 4; ni++) { s_[ni][0] = s_[ni][1] = q_[ni][0] = q_[ni][1] = 0.f; }
    }
#pragma unroll
    for (int mi = 0; mi < 4; mi++) {
        int row = row0 + wm * 64 + mi * 16 + (lane >> 2);
#pragma unroll
        for (int ni = 0; ni < 4; ni++) {
            int col = col0 + wn * 32 + ni * 8 + (lane & 3) * 2;
            float b0 = bias[col], b1 = bias[col + 1];
            float v0 = acc[mi][ni][0] + b0, v1 = acc[mi][ni][1] + b1;
            float v2 = acc[mi][ni][2] + b0, v3 = acc[mi][ni][3] + b1;
            if (RELU) {
                v0 = fmaxf(v0, 0.f); v1 = fmaxf(v1, 0.f);
                v2 = fmaxf(v2, 0.f); v3 = fmaxf(v3, 0.f);
            }
            if (STATS) {
                s_[ni][0] += v0 + v2; s_[ni][1] += v1 + v3;
                q_[ni][0] += v0 * v0 + v2 * v2; q_[ni][1] += v1 * v1 + v3 * v3;
            }
            float2 lo2 = make_float2(v0, v1);
            float2 hi2 = make_float2(v2, v3);
            *(float2*)(C + (size_t)row * Nn + col) = lo2;
            *(float2*)(C + (size_t)(row + 8) * Nn + col) = hi2;
        }
    }
    if (STATS) {
#pragma unroll
        for (int ni = 0; ni < 4; ni++) {
#pragma unroll
            for (int j = 0; j < 2; j++) {
#pragma unroll
                for (int off = 4; off <= 16; off <<= 1) {
                    s_[ni][j] += __shfl_xor_sync(0xffffffffu, s_[ni][j], off);
                    q_[ni][j] += __shfl_xor_sync(0xffffffffu, q_[ni][j], off);
                }
            }
        }
        if ((lane >> 2) == 0) {
#pragma unroll
            for (int ni = 0; ni < 4; ni++) {
                int col = col0 + wn * 32 + ni * 8 + (lane & 3) * 2;
                atomicAdd(&g_sum[col],     s_[ni][0]);
                atomicAdd(&g_sum[col + 1], s_[ni][1]);
                atomicAdd(&g_sumsq[col],     q_[ni][0]);
                atomicAdd(&g_sumsq[col + 1], q_[ni][1]);
            }
        }
    }
}

// ---------------- final tiny GEMM: out[M,5] = h[M,256] @ Wc2[5,256]^T + bc2 -----
__global__ void final_kernel(const float* __restrict__ Wc2, const float* __restrict__ bc2,
                             float* __restrict__ out) {
    __shared__ float w[5 * 256];
    for (int i = threadIdx.x; i < 5 * 256; i += blockDim.x) w[i] = Wc2[i];
    __syncthreads();
    int warp = threadIdx.x >> 5, lane = threadIdx.x & 31;
    int r = blockIdx.x * (blockDim.x >> 5) + warp;
    const float* h = g_h + (size_t)r * 256;
    float a0 = 0, a1 = 0, a2 = 0, a3 = 0, a4 = 0;
    for (int c = lane; c < 256; c += 32) {
        float hv = h[c];
        a0 = fmaf(hv, w[0 * 256 + c], a0);
        a1 = fmaf(hv, w[1 * 256 + c], a1);
        a2 = fmaf(hv, w[2 * 256 + c], a2);
        a3 = fmaf(hv, w[3 * 256 + c], a3);
        a4 = fmaf(hv, w[4 * 256 + c], a4);
    }
#pragma unroll
    for (int off = 16; off; off >>= 1) {
        a0 += __shfl_xor_sync(0xffffffffu, a0, off);
        a1 += __shfl_xor_sync(0xffffffffu, a1, off);
        a2 += __shfl_xor_sync(0xffffffffu, a2, off);
        a3 += __shfl_xor_sync(0xffffffffu, a3, off);
        a4 += __shfl_xor_sync(0xffffffffu, a4, off);
    }
    if (lane == 0) {
        float* o = out + (size_t)r * 5;
        o[0] = a0 + bc2[0];
        o[1] = a1 + bc2[1];
        o[2] = a2 + bc2[2];
        o[3] = a3 + bc2[3];
        o[4] = a4 + bc2[4];
    }
}

// ---------------- launch ----------------
extern "C" void kernel_launch(void* const* d_in, const int* in_sizes, int n_in,
                              void* d_out, int out_size) {
    const float* x    = (const float*)d_in[0];
    const float* pos  = (const float*)d_in[1];
    const float* W[3]  = {(const float*)d_in[2], (const float*)d_in[6], (const float*)d_in[10]};
    const float* bb[3] = {(const float*)d_in[3], (const float*)d_in[7], (const float*)d_in[11]};
    const float* gg[3] = {(const float*)d_in[4], (const float*)d_in[8], (const float*)d_in[12]};
    const float* be[3] = {(const float*)d_in[5], (const float*)d_in[9], (const float*)d_in[13]};
    const float* Wc1 = (const float*)d_in[14];
    const float* bc1 = (const float*)d_in[15];
    const float* Wc2 = (const float*)d_in[16];
    const float* bc2 = (const float*)d_in[17];
    float* out = (float*)d_out;

    float *p_y, *p_h;
    __nv_bfloat16 *p_Ahi, *p_Alo, *p_Xhi, *p_Xlo, *p_Whi, *p_Wlo, *p_Chi, *p_Clo;
    cudaGetSymbolAddress((void**)&p_y, g_y);
    cudaGetSymbolAddress((void**)&p_h, g_h);
    cudaGetSymbolAddress((void**)&p_Ahi, g_Ahi);
    cudaGetSymbolAddress((void**)&p_Alo, g_Alo);
    cudaGetSymbolAddress((void**)&p_Xhi, g_Xhi);
    cudaGetSymbolAddress((void**)&p_Xlo, g_Xlo);
    cudaGetSymbolAddress((void**)&p_Whi, g_Whi);
    cudaGetSymbolAddress((void**)&p_Wlo, g_Wlo);
    cudaGetSymbolAddress((void**)&p_Chi, g_Chi);
    cudaGetSymbolAddress((void**)&p_Clo, g_Clo);

    cudaFuncSetAttribute(mma_gemm<0, 1>, cudaFuncAttributeMaxDynamicSharedMemorySize, SMEM_GEMM_BYTES);
    cudaFuncSetAttribute(mma_gemm<1, 0>, cudaFuncAttributeMaxDynamicSharedMemorySize, SMEM_GEMM_BYTES);

    transpose_kernel<<<dim3(NPTS / 32, CH / 32, BATCH), dim3(32, 8)>>>(x);
    knn_kernel<<<dim3(NPTS / 8, BATCH), 256>>>(pos);
    wsplit_all<<<(3 * W_ELEMS + C_ELEMS) / 256, 256>>>(W[0], W[1], W[2], Wc1);

    for (int i = 0; i < 3; i++) {
        if (i == 0) feat_kernel<<<MROWS, 128>>>();
        else        bnfeat_kernel<<<MROWS, 128>>>(gg[i - 1], be[i - 1]);
        zero_stats<<<1, CH>>>();
        mma_gemm<0, 1><<<dim3(CH / 128, MROWS / 128), 256, SMEM_GEMM_BYTES>>>(
            p_Ahi, p_Alo, p_Whi + (size_t)i * CH * KDIM, p_Wlo + (size_t)i * CH * KDIM,
            bb[i], p_y, KDIM, CH);
    }

    // classifier: Xhi/Xlo = bn+relu(layer3), then h = relu(X @ Wc1^T + bc1)
    bn_apply_cls<<<(MROWS * CH) / 256, 256>>>(gg[2], be[2]);
    mma_gemm<1, 0><<<dim3((CH / 2) / 128, MROWS / 128), 256, SMEM_GEMM_BYTES>>>(
        p_Xhi, p_Xlo, p_Chi, p_Clo, bc1, p_h, CH, CH / 2);
    final_kernel<<<MROWS / 8, 256>>>(Wc2, bc2, out);
}

// round 8
// speedup vs baseline: 2.2571x; 1.0165x over previous
#include <cuda_runtime.h>
#include <cuda_bf16.h>
#include <cstdint>

#define BATCH 4
#define CH    512
#define NPTS  4096
#define MROWS (BATCH * NPTS)   // 16384
#define KNN   5
#define KDIM  (2 * CH)         // 1024

// ================= PTX helpers (baseline ISA only — no sm_103a features) =========
__device__ __forceinline__ uint32_t smem_u32(const void* p) {
    return (uint32_t)__cvta_generic_to_shared((void*)p);
}
#define SWZ(o) ((o) ^ (((o) >> 3) & 0x70))

__device__ __forceinline__ void ldsm_x4(uint32_t (&r)[4], uint32_t addr) {
    asm volatile("ldmatrix.sync.aligned.m8n8.x4.shared.b16 {%0,%1,%2,%3}, [%4];"
                 : "=r"(r[0]), "=r"(r[1]), "=r"(r[2]), "=r"(r[3]) : "r"(addr));
}
__device__ __forceinline__ void mma16816(float (&c)[4], const uint32_t (&a)[4],
                                         uint32_t b0, uint32_t b1) {
    asm volatile("mma.sync.aligned.m16n8k16.row.col.f32.bf16.bf16.f32 "
                 "{%0,%1,%2,%3}, {%4,%5,%6,%7}, {%8,%9}, {%0,%1,%2,%3};"
                 : "+f"(c[0]), "+f"(c[1]), "+f"(c[2]), "+f"(c[3])
                 : "r"(a[0]), "r"(a[1]), "r"(a[2]), "r"(a[3]), "r"(b0), "r"(b1));
}
#define CP_ASYNC16(dst, src) \
    asm volatile("cp.async.cg.shared.global [%0], [%1], 16;" :: "r"(dst), "l"(src))
#define CP_COMMIT() asm volatile("cp.async.commit_group;" ::: "memory")
#define CP_WAIT2()  asm volatile("cp.async.wait_group 2;" ::: "memory")
#define CP_WAIT1()  asm volatile("cp.async.wait_group 1;" ::: "memory")
#define CP_WAIT0()  asm volatile("cp.async.wait_group 0;" ::: "memory")

// ================= scratch (static device globals; no allocation) =================
__device__ float g_xt[(size_t)MROWS * CH];
__device__ __align__(16) __nv_bfloat16 g_Ahi[(size_t)MROWS * KDIM];
__device__ __align__(16) __nv_bfloat16 g_Alo[(size_t)MROWS * KDIM];
__device__ __align__(16) __nv_bfloat16 g_Xhi[(size_t)MROWS * CH];
__device__ __align__(16) __nv_bfloat16 g_Xlo[(size_t)MROWS * CH];
__device__ __align__(16) __nv_bfloat16 g_Whi[(size_t)3 * CH * KDIM];
__device__ __align__(16) __nv_bfloat16 g_Wlo[(size_t)3 * CH * KDIM];
__device__ __align__(16) __nv_bfloat16 g_Chi[(size_t)(CH / 2) * CH];
__device__ __align__(16) __nv_bfloat16 g_Clo[(size_t)(CH / 2) * CH];
__device__ float g_y[(size_t)MROWS * CH];
__device__ float g_h[(size_t)MROWS * (CH / 2)];
__device__ int   g_idx[MROWS * KNN];
__device__ float g_sum[CH];
__device__ float g_sumsq[CH];

__device__ __forceinline__ void split_bf16(float x, __nv_bfloat16& h, __nv_bfloat16& l) {
    h = __float2bfloat16(x);
    l = __float2bfloat16(x - __bfloat162float(h));
}

// ---------------- transpose: x [B,C,N] -> g_xt [B*N, C] ----------------
__global__ void transpose_kernel(const float* __restrict__ x) {
    __shared__ float tile[32][33];
    int b = blockIdx.z;
    int n0 = blockIdx.x * 32, c0 = blockIdx.y * 32;
    int tx = threadIdx.x, ty = threadIdx.y;  // (32, 8)
#pragma unroll
    for (int i = 0; i < 4; i++) {
        int c = c0 + ty + i * 8;
        tile[ty + i * 8][tx] = x[((size_t)(b * CH + c)) * NPTS + n0 + tx];
    }
    __syncthreads();
#pragma unroll
    for (int i = 0; i < 4; i++) {
        int n = n0 + ty + i * 8;
        g_xt[((size_t)(b * NPTS + n)) * CH + c0 + tx] = tile[tx][ty + i * 8];
    }
}

// ---------------- KNN (bit-exact vs reference; DO NOT TOUCH) ----------------
#define LTC(da, ia, db, ib) ((da) < (db) || ((da) == (db) && (ia) < (ib)))

__global__ void knn_kernel(const float* __restrict__ pos) {
    __shared__ float sx[NPTS];
    __shared__ float sy[NPTS];
    __shared__ float sd[NPTS];
    int b = blockIdx.y;
    const float* p = pos + (size_t)b * NPTS * 2;
    for (int j = threadIdx.x; j < NPTS; j += blockDim.x) {
        float xx = p[2 * j], yy = p[2 * j + 1];
        sx[j] = xx; sy[j] = yy;
        sd[j] = __fadd_rn(__fmul_rn(xx, xx), __fmul_rn(yy, yy));  // add-form d2
    }
    __syncthreads();

    int warp = threadIdx.x >> 5, lane = threadIdx.x & 31;
    int q = blockIdx.x * (blockDim.x >> 5) + warp;

    float xi = sx[q], yi = sy[q], d2i = sd[q];
    const float INF = __int_as_float(0x7f800000);
    float d0 = INF, d1 = INF, d2 = INF, d3 = INF, d4 = INF;
    int   i0 = 0x7fffffff, i1 = 0x7fffffff, i2 = 0x7fffffff, i3 = 0x7fffffff, i4 = 0x7fffffff;

    for (int j = lane; j < NPTS; j += 32) {
        float dot  = __fmaf_rn(yi, sy[j], __fmul_rn(xi, sx[j]));  // fma-form dot
        float dist = __fadd_rn(__fadd_rn(d2i, sd[j]), -__fmul_rn(2.0f, dot));
        if (LTC(dist, j, d4, i4)) {
            d4 = dist; i4 = j;
            if (LTC(d4, i4, d3, i3)) { float tf = d3; d3 = d4; d4 = tf; int ti = i3; i3 = i4; i4 = ti; }
            if (LTC(d3, i3, d2, i2)) { float tf = d2; d2 = d3; d3 = tf; int ti = i2; i2 = i3; i3 = ti; }
            if (LTC(d2, i2, d1, i1)) { float tf = d1; d1 = d2; d2 = tf; int ti = i1; i1 = i2; i2 = ti; }
            if (LTC(d1, i1, d0, i0)) { float tf = d0; d0 = d1; d1 = tf; int ti = i0; i0 = i1; i1 = ti; }
        }
    }
#pragma unroll
    for (int k = 0; k < KNN; k++) {
        float od = d0; int oi = i0;
#pragma unroll
        for (int off = 16; off; off >>= 1) {
            float td = __shfl_down_sync(0xffffffffu, od, off);
            int   ti = __shfl_down_sync(0xffffffffu, oi, off);
            if (LTC(td, ti, od, oi)) { od = td; oi = ti; }
        }
        od = __shfl_sync(0xffffffffu, od, 0);
        oi = __shfl_sync(0xffffffffu, oi, 0);
        if (oi == i0) {
            d0 = d1; i0 = i1; d1 = d2; i1 = i2; d2 = d3; i2 = i3; d3 = d4; i3 = i4;
            d4 = INF; i4 = 0x7fffffff;
        }
        if (lane == 0) g_idx[((size_t)(b * NPTS + q)) * KNN + k] = oi;
    }
}

// ---------------- feat (layer 1): gather + maxrel from fp32 g_xt ----------------
__global__ void feat_kernel() {
    int r = blockIdx.x;
    __shared__ int nb[KNN];
    if (threadIdx.x < KNN) nb[threadIdx.x] = (r >> 12) * NPTS + g_idx[r * KNN + threadIdx.x];
    __syncthreads();
    int n0 = nb[0], n1 = nb[1], n2 = nb[2], n3 = nb[3], n4 = nb[4];
    const float* xr = g_xt + (size_t)r * CH;
    __nv_bfloat162* ah = (__nv_bfloat162*)(g_Ahi + (size_t)r * KDIM);
    __nv_bfloat162* al = (__nv_bfloat162*)(g_Alo + (size_t)r * KDIM);
    for (int c = threadIdx.x; c < CH; c += blockDim.x) {
        float s = xr[c];
        float m = g_xt[(size_t)n0 * CH + c] - s;
        m = fmaxf(m, g_xt[(size_t)n1 * CH + c] - s);
        m = fmaxf(m, g_xt[(size_t)n2 * CH + c] - s);
        m = fmaxf(m, g_xt[(size_t)n3 * CH + c] - s);
        m = fmaxf(m, g_xt[(size_t)n4 * CH + c] - s);
        __nv_bfloat16 sh, sl, mh, ml;
        split_bf16(s, sh, sl);
        split_bf16(m, mh, ml);
        __nv_bfloat162 vh; vh.x = sh; vh.y = mh;
        __nv_bfloat162 vl; vl.x = sl; vl.y = ml;
        ah[c] = vh; al[c] = vl;
    }
}

// ---------------- bnfeat (layers 2,3): BN(g_y)+relu on the fly, gather + maxrel ---
__global__ void bnfeat_kernel(const float* __restrict__ gamma, const float* __restrict__ beta) {
    int r = blockIdx.x;
    __shared__ int nb[KNN];
    if (threadIdx.x < KNN) nb[threadIdx.x] = (r >> 12) * NPTS + g_idx[r * KNN + threadIdx.x];
    __syncthreads();
    int n0 = nb[0], n1 = nb[1], n2 = nb[2], n3 = nb[3], n4 = nb[4];
    const float* yr = g_y + (size_t)r * CH;
    __nv_bfloat162* ah = (__nv_bfloat162*)(g_Ahi + (size_t)r * KDIM);
    __nv_bfloat162* al = (__nv_bfloat162*)(g_Alo + (size_t)r * KDIM);
    const float inv = 1.0f / (float)MROWS;
    for (int c = threadIdx.x; c < CH; c += blockDim.x) {
        float mean = g_sum[c] * inv;
        float var  = g_sumsq[c] * inv - mean * mean;
        float rs = rsqrtf(var + 1e-5f);
        float gm = gamma[c], bt = beta[c];
        float s  = fmaxf((yr[c] - mean) * rs * gm + bt, 0.f);
        float a0 = fmaxf((g_y[(size_t)n0 * CH + c] - mean) * rs * gm + bt, 0.f);
        float a1 = fmaxf((g_y[(size_t)n1 * CH + c] - mean) * rs * gm + bt, 0.f);
        float a2 = fmaxf((g_y[(size_t)n2 * CH + c] - mean) * rs * gm + bt, 0.f);
        float a3 = fmaxf((g_y[(size_t)n3 * CH + c] - mean) * rs * gm + bt, 0.f);
        float a4 = fmaxf((g_y[(size_t)n4 * CH + c] - mean) * rs * gm + bt, 0.f);
        float m = fmaxf(fmaxf(fmaxf(a0 - s, a1 - s), fmaxf(a2 - s, a3 - s)), a4 - s);
        __nv_bfloat16 sh, sl, mh, ml;
        split_bf16(s, sh, sl);
        split_bf16(m, mh, ml);
        __nv_bfloat162 vh; vh.x = sh; vh.y = mh;
        __nv_bfloat162 vl; vl.x = sl; vl.y = ml;
        ah[c] = vh; al[c] = vl;
    }
}

// ---------------- bn_apply for classifier (layer 3 output -> Xhi/Xlo) ----------
__global__ void bn_apply_cls(const float* __restrict__ gamma, const float* __restrict__ beta) {
    int i = blockIdx.x * blockDim.x + threadIdx.x;
    int c = i & (CH - 1);
    const float inv = 1.0f / (float)MROWS;
    float mean = g_sum[c] * inv;
    float var  = g_sumsq[c] * inv - mean * mean;
    float v = fmaxf((g_y[i] - mean) * rsqrtf(var + 1e-5f) * gamma[c] + beta[c], 0.f);
    __nv_bfloat16 h, l;
    split_bf16(v, h, l);
    g_Xhi[i] = h; g_Xlo[i] = l;
}

// ---------------- all weight splits in one launch ----------------
#define W_ELEMS (CH * KDIM)            // 524288
#define C_ELEMS ((CH / 2) * CH)        // 131072
__global__ void wsplit_all(const float* __restrict__ w1, const float* __restrict__ w2,
                           const float* __restrict__ w3, const float* __restrict__ wc1) {
    int i = blockIdx.x * blockDim.x + threadIdx.x;
    const float* src; __nv_bfloat16 *hi, *lo; int k;
    if (i < W_ELEMS)            { src = w1;  hi = g_Whi;               lo = g_Wlo;               k = i; }
    else if (i < 2 * W_ELEMS)   { src = w2;  hi = g_Whi + W_ELEMS;     lo = g_Wlo + W_ELEMS;     k = i - W_ELEMS; }
    else if (i < 3 * W_ELEMS)   { src = w3;  hi = g_Whi + 2 * W_ELEMS; lo = g_Wlo + 2 * W_ELEMS; k = i - 2 * W_ELEMS; }
    else if (i < 3 * W_ELEMS + C_ELEMS) { src = wc1; hi = g_Chi;       lo = g_Clo;               k = i - 3 * W_ELEMS; }
    else return;
    __nv_bfloat16 h, l;
    split_bf16(src[k], h, l);
    hi[k] = h; lo[k] = l;
}

__global__ void zero_stats() {
    g_sum[threadIdx.x] = 0.f;
    g_sumsq[threadIdx.x] = 0.f;
}

// ================= HMMA split-bf16 GEMM, 128x256 tile, 3-stage pipe, fused stats ==
// C[M,Nn] fp32 = Ahi*Bhi^T + Alo*Bhi^T + Ahi*Blo^T + bias, optional relu.
// 8 warps (2M x 4N), warp tile 64x64. K chunks of 64 bf16.
#define A_STAGE 16384
#define B_STAGE 32768
#define STAGE_BYTES (A_STAGE + B_STAGE)          // 48 KB
#define SMEM_GEMM_BYTES (3 * STAGE_BYTES)        // 144 KB

template <int RELU, int STATS>
__global__ void __launch_bounds__(256) mma_gemm(
    const __nv_bfloat16* __restrict__ Ahi, const __nv_bfloat16* __restrict__ Alo,
    const __nv_bfloat16* __restrict__ Bhi, const __nv_bfloat16* __restrict__ Blo,
    const float* __restrict__ bias, float* __restrict__ C, int Kd, int Nn) {
    extern __shared__ char smem[];
    uint32_t sb = smem_u32(smem);
    int tid = threadIdx.x, lane = tid & 31, wid = tid >> 5;
    int wm = wid & 1, wn = wid >> 1;  // 2 x 4 warp grid, warp tile 64x64
    int row0 = blockIdx.y * 128, col0 = blockIdx.x * 256;
    int KC = Kd >> 6, NIT = 3 * KC;

    float acc[4][8][4];
#pragma unroll
    for (int mi = 0; mi < 4; mi++)
#pragma unroll
        for (int ni = 0; ni < 8; ni++)
#pragma unroll
            for (int j = 0; j < 4; j++) acc[mi][ni][j] = 0.f;

    int lr = tid >> 3, lg = tid & 7;

    auto load_chunk = [&](int idx, int st) {
        int p = idx / KC, kc = idx - p * KC;
        const __nv_bfloat16* As = (p == 1) ? Alo : Ahi;
        const __nv_bfloat16* Bs = (p == 2) ? Blo : Bhi;
        uint32_t abase = sb + st * STAGE_BYTES;
        uint32_t bbase = abase + A_STAGE;
#pragma unroll
        for (int i = 0; i < 4; i++) {
            int r = lr + i * 32;
            CP_ASYNC16(abase + SWZ((uint32_t)(r * 128 + lg * 16)),
                       As + (size_t)(row0 + r) * Kd + kc * 64 + lg * 8);
        }
#pragma unroll
        for (int i = 0; i < 8; i++) {
            int r = lr + i * 32;
            CP_ASYNC16(bbase + SWZ((uint32_t)(r * 128 + lg * 16)),
                       Bs + (size_t)(col0 + r) * Kd + kc * 64 + lg * 8);
        }
        CP_COMMIT();
    };

    load_chunk(0, 0);
    load_chunk(1, 1);

    for (int it = 0; it < NIT; it++) {
        int s = it % 3;
        if (it + 2 < NIT) { load_chunk(it + 2, (it + 2) % 3); CP_WAIT2(); }
        else if (it + 1 < NIT) { CP_WAIT1(); }
        else { CP_WAIT0(); }
        __syncthreads();

        uint32_t abase = sb + s * STAGE_BYTES;
        uint32_t bbase = abase + A_STAGE;
#pragma unroll
        for (int kk = 0; kk < 4; kk++) {
            uint32_t af[4][4];
#pragma unroll
            for (int mi = 0; mi < 4; mi++) {
                int r = wm * 64 + mi * 16 + (lane & 15);
                uint32_t off = (uint32_t)(r * 128 + kk * 32 + (lane >> 4) * 16);
                ldsm_x4(af[mi], abase + SWZ(off));
            }
#pragma unroll
            for (int p = 0; p < 4; p++) {
                // B ldsm_x4: rows p*16..p*16+15 of warp N-tile, both k-halves
                // r[0]=ni=2p k0, r[1]=ni=2p+1 k0, r[2]=ni=2p k1, r[3]=ni=2p+1 k1
                uint32_t bf[4];
                int r = wn * 64 + p * 16 + (lane & 15);
                uint32_t off = (uint32_t)(r * 128 + kk * 32 + (lane >> 4) * 16);
                ldsm_x4(bf, bbase + SWZ(off));
#pragma unroll
                for (int mi = 0; mi < 4; mi++) {
                    mma16816(acc[mi][2 * p], af[mi], bf[0], bf[2]);
                    mma16816(acc[mi][2 * p + 1], af[mi], bf[1], bf[3]);
                }
            }
        }
        __syncthreads();
    }

    // epilogue: +bias, optional relu, store; optional fused column stats
    float s_[8][2], q_[8][2];
    if (STATS) {
#pragma unroll
        for (int ni = 0; ni < 8; ni++) { s_[ni][0] = s_[ni][1] = q_[ni][0] = q_[ni][1] = 0.f; }
    }
#pragma unroll
    for (int mi = 0; mi < 4; mi++) {
        int row = row0 + wm * 64 + mi * 16 + (lane >> 2);
#pragma unroll
        for (int ni = 0; ni < 8; ni++) {
            int col = col0 + wn * 64 + ni * 8 + (lane & 3) * 2;
            float b0 = bias[col], b1 = bias[col + 1];
            float v0 = acc[mi][ni][0] + b0, v1 = acc[mi][ni][1] + b1;
            float v2 = acc[mi][ni][2] + b0, v3 = acc[mi][ni][3] + b1;
            if (RELU) {
                v0 = fmaxf(v0, 0.f); v1 = fmaxf(v1, 0.f);
                v2 = fmaxf(v2, 0.f); v3 = fmaxf(v3, 0.f);
            }
            if (STATS) {
                s_[ni][0] += v0 + v2; s_[ni][1] += v1 + v3;
                q_[ni][0] += v0 * v0 + v2 * v2; q_[ni][1] += v1 * v1 + v3 * v3;
            }
            *(float2*)(C + (size_t)row * Nn + col) = make_float2(v0, v1);
            *(float2*)(C + (size_t)(row + 8) * Nn + col) = make_float2(v2, v3);
        }
    }
    if (STATS) {
#pragma unroll
        for (int ni = 0; ni < 8; ni++) {
#pragma unroll
            for (int j = 0; j < 2; j++) {
#pragma unroll
                for (int off = 4; off <= 16; off <<= 1) {
                    s_[ni][j] += __shfl_xor_sync(0xffffffffu, s_[ni][j], off);
                    q_[ni][j] += __shfl_xor_sync(0xffffffffu, q_[ni][j], off);
                }
            }
        }
        if ((lane >> 2) == 0) {
#pragma unroll
            for (int ni = 0; ni < 8; ni++) {
                int col = col0 + wn * 64 + ni * 8 + (lane & 3) * 2;
                atomicAdd(&g_sum[col],     s_[ni][0]);
                atomicAdd(&g_sum[col + 1], s_[ni][1]);
                atomicAdd(&g_sumsq[col],     q_[ni][0]);
                atomicAdd(&g_sumsq[col + 1], q_[ni][1]);
            }
        }
    }
}

// ---------------- final tiny GEMM: out[M,5] = h[M,256] @ Wc2[5,256]^T + bc2 -----
__global__ void final_kernel(const float* __restrict__ Wc2, const float* __restrict__ bc2,
                             float* __restrict__ out) {
    __shared__ float w[5 * 256];
    for (int i = threadIdx.x; i < 5 * 256; i += blockDim.x) w[i] = Wc2[i];
    __syncthreads();
    int warp = threadIdx.x >> 5, lane = threadIdx.x & 31;
    int r = blockIdx.x * (blockDim.x >> 5) + warp;
    const float* h = g_h + (size_t)r * 256;
    float a0 = 0, a1 = 0, a2 = 0, a3 = 0, a4 = 0;
    for (int c = lane; c < 256; c += 32) {
        float hv = h[c];
        a0 = fmaf(hv, w[0 * 256 + c], a0);
        a1 = fmaf(hv, w[1 * 256 + c], a1);
        a2 = fmaf(hv, w[2 * 256 + c], a2);
        a3 = fmaf(hv, w[3 * 256 + c], a3);
        a4 = fmaf(hv, w[4 * 256 + c], a4);
    }
#pragma unroll
    for (int off = 16; off; off >>= 1) {
        a0 += __shfl_xor_sync(0xffffffffu, a0, off);
        a1 += __shfl_xor_sync(0xffffffffu, a1, off);
        a2 += __shfl_xor_sync(0xffffffffu, a2, off);
        a3 += __shfl_xor_sync(0xffffffffu, a3, off);
        a4 += __shfl_xor_sync(0xffffffffu, a4, off);
    }
    if (lane == 0) {
        float* o = out + (size_t)r * 5;
        o[0] = a0 + bc2[0];
        o[1] = a1 + bc2[1];
        o[2] = a2 + bc2[2];
        o[3] = a3 + bc2[3];
        o[4] = a4 + bc2[4];
    }
}

// ---------------- launch ----------------
extern "C" void kernel_launch(void* const* d_in, const int* in_sizes, int n_in,
                              void* d_out, int out_size) {
    const float* x    = (const float*)d_in[0];
    const float* pos  = (const float*)d_in[1];
    const float* W[3]  = {(const float*)d_in[2], (const float*)d_in[6], (const float*)d_in[10]};
    const float* bb[3] = {(const float*)d_in[3], (const float*)d_in[7], (const float*)d_in[11]};
    const float* gg[3] = {(const float*)d_in[4], (const float*)d_in[8], (const float*)d_in[12]};
    const float* be[3] = {(const float*)d_in[5], (const float*)d_in[9], (const float*)d_in[13]};
    const float* Wc1 = (const float*)d_in[14];
    const float* bc1 = (const float*)d_in[15];
    const float* Wc2 = (const float*)d_in[16];
    const float* bc2 = (const float*)d_in[17];
    float* out = (float*)d_out;

    float *p_y, *p_h;
    __nv_bfloat16 *p_Ahi, *p_Alo, *p_Xhi, *p_Xlo, *p_Whi, *p_Wlo, *p_Chi, *p_Clo;
    cudaGetSymbolAddress((void**)&p_y, g_y);
    cudaGetSymbolAddress((void**)&p_h, g_h);
    cudaGetSymbolAddress((void**)&p_Ahi, g_Ahi);
    cudaGetSymbolAddress((void**)&p_Alo, g_Alo);
    cudaGetSymbolAddress((void**)&p_Xhi, g_Xhi);
    cudaGetSymbolAddress((void**)&p_Xlo, g_Xlo);
    cudaGetSymbolAddress((void**)&p_Whi, g_Whi);
    cudaGetSymbolAddress((void**)&p_Wlo, g_Wlo);
    cudaGetSymbolAddress((void**)&p_Chi, g_Chi);
    cudaGetSymbolAddress((void**)&p_Clo, g_Clo);

    cudaFuncSetAttribute(mma_gemm<0, 1>, cudaFuncAttributeMaxDynamicSharedMemorySize, SMEM_GEMM_BYTES);
    cudaFuncSetAttribute(mma_gemm<1, 0>, cudaFuncAttributeMaxDynamicSharedMemorySize, SMEM_GEMM_BYTES);

    transpose_kernel<<<dim3(NPTS / 32, CH / 32, BATCH), dim3(32, 8)>>>(x);
    knn_kernel<<<dim3(NPTS / 8, BATCH), 256>>>(pos);
    wsplit_all<<<(3 * W_ELEMS + C_ELEMS) / 256, 256>>>(W[0], W[1], W[2], Wc1);

    for (int i = 0; i < 3; i++) {
        if (i == 0) feat_kernel<<<MROWS, 128>>>();
        else        bnfeat_kernel<<<MROWS, 128>>>(gg[i - 1], be[i - 1]);
        zero_stats<<<1, CH>>>();
        mma_gemm<0, 1><<<dim3(CH / 256, MROWS / 128), 256, SMEM_GEMM_BYTES>>>(
            p_Ahi, p_Alo, p_Whi + (size_t)i * CH * KDIM, p_Wlo + (size_t)i * CH * KDIM,
            bb[i], p_y, KDIM, CH);
    }

    // classifier: Xhi/Xlo = bn+relu(layer3), then h = relu(X @ Wc1^T + bc1)
    bn_apply_cls<<<(MROWS * CH) / 256, 256>>>(gg[2], be[2]);
    mma_gemm<1, 0><<<dim3((CH / 2) / 256 + ((CH / 2) % 256 != 0), MROWS / 128), 256, SMEM_GEMM_BYTES>>>(
        p_Xhi, p_Xlo, p_Chi, p_Clo, bc1, p_h, CH, CH / 2);
    final_kernel<<<MROWS / 8, 256>>>(Wc2, bc2, out);
}